// round 4
// baseline (speedup 1.0000x reference)
#include <cuda_runtime.h>
#include <cuda_fp16.h>

#define DFT 784
#define DP  800              // padded feature dim (zero-padded tail)
#define PAD 64               // over-allocation so prefetch needs no guard
#define KC  50
#define LF  6
#define NB  2
#define THREADS 160
#define NWARPS (THREADS/32)  // 5 -> each warp does exactly 10 components
#define NITER 25             // DP/32
#define NCAND 3              // exact-rescore candidates per sample

typedef unsigned long long u64;

// Exact fp32 operands (rescore + reference-exact path):
//  g_C0 = {c0,c1,c2,c3}, g_C1 = {c4,c5,s,nsmu}, g_LD = logD
// where c_i = sqrt(invD)*a_i, s = sqrt(invD), nsmu = -s*mu.
__device__ __align__(16) float4 g_C0[KC * DP + PAD];
__device__ __align__(16) float4 g_C1[KC * DP + PAD];
__device__ float g_LD[KC * DP + PAD];
// Compressed hot-loop operands: g_H = {h2(c0,c1),h2(c2,c3),h2(c4,c5), s}, g_NS = nsmu
__device__ __align__(16) float4 g_H[KC * DP + PAD];
__device__ float g_NS[KC * DP + PAD];

__device__ __forceinline__ constexpr int IJ(int i, int j) { return i * (i + 1) / 2 + j; }

// ---- f32x2 packed helpers ----
__device__ __forceinline__ u64 pk2(float a, float b) {
    u64 r; asm("mov.b64 %0,{%1,%2};" : "=l"(r) : "f"(a), "f"(b)); return r;
}
__device__ __forceinline__ u64 rep2(float a) { return pk2(a, a); }
__device__ __forceinline__ void upk2(u64 v, float& a, float& b) {
    asm("mov.b64 {%0,%1},%2;" : "=f"(a), "=f"(b) : "l"(v));
}
__device__ __forceinline__ u64 fma2(u64 a, u64 b, u64 c) {
    u64 d; asm("fma.rn.f32x2 %0,%1,%2,%3;" : "=l"(d) : "l"(a), "l"(b), "l"(c)); return d;
}
__device__ __forceinline__ u64 mul2(u64 a, u64 b) {
    u64 d; asm("mul.rn.f32x2 %0,%1,%2;" : "=l"(d) : "l"(a), "l"(b)); return d;
}
__device__ __forceinline__ u64 add2(u64 a, u64 b) {
    u64 d; asm("add.rn.f32x2 %0,%1,%2;" : "=l"(d) : "l"(a), "l"(b)); return d;
}
__device__ __forceinline__ float2 bits2f2(float bits) {
    __half2 h = *reinterpret_cast<const __half2*>(&bits);
    return __half22float2(h);
}
__device__ __forceinline__ float2 u2f2(unsigned bits) {
    __half2 h = *reinterpret_cast<const __half2*>(&bits);
    return __half22float2(h);
}

__global__ void pack_kernel(const float* __restrict__ A_fac,
                            const float* __restrict__ MU,
                            const float* __restrict__ log_D)
{
    int idx = blockIdx.x * blockDim.x + threadIdx.x;
    if (idx >= KC * DP + PAD) return;
    int k = idx / DP, d = idx - k * DP;
    if (k < KC && d < DFT) {
        int src = k * DFT + d;
        const float* a = A_fac + (size_t)src * LF;
        float ld = log_D[src];
        float s  = expf(-0.5f * ld);       // sqrt(invD)
        float c0 = s * a[0], c1 = s * a[1], c2 = s * a[2];
        float c3 = s * a[3], c4 = s * a[4], c5 = s * a[5];
        float nsmu = -s * MU[src];
        g_C0[idx] = make_float4(c0, c1, c2, c3);
        g_C1[idx] = make_float4(c4, c5, s, nsmu);
        g_LD[idx] = ld;
        __half2 h01 = __floats2half2_rn(c0, c1);
        __half2 h23 = __floats2half2_rn(c2, c3);
        __half2 h45 = __floats2half2_rn(c4, c5);
        g_H[idx] = make_float4(*reinterpret_cast<float*>(&h01),
                               *reinterpret_cast<float*>(&h23),
                               *reinterpret_cast<float*>(&h45), s);
        g_NS[idx] = nsmu;
    } else {
        g_C0[idx] = make_float4(0.f, 0.f, 0.f, 0.f);
        g_C1[idx] = make_float4(0.f, 0.f, 0.f, 0.f);
        g_LD[idx] = 0.f;
        g_H[idx]  = make_float4(0.f, 0.f, 0.f, 1.0f);   // s=1 so lg2(s)=0 (no inf/NaN)
        g_NS[idx] = 0.f;
    }
}

// Cholesky (lower) of packed 6x6 SPD, in place. Returns product of pivots (= det),
// fills inv[j] = 1/L[j][j].
__device__ __forceinline__ float chol6(float* S, float* inv)
{
    float prod = 1.f;
    #pragma unroll
    for (int j = 0; j < LF; j++) {
        float s = S[IJ(j, j)];
        #pragma unroll
        for (int m = 0; m < j; m++) s = fmaf(-S[IJ(j, m)], S[IJ(j, m)], s);
        prod *= s;
        float rs = rsqrtf(s);
        inv[j] = rs;
        S[IJ(j, j)] = s * rs;
        #pragma unroll
        for (int i = j + 1; i < LF; i++) {
            float t = S[IJ(i, j)];
            #pragma unroll
            for (int m = 0; m < j; m++) t = fmaf(-S[IJ(i, m)], S[IJ(j, m)], t);
            S[IJ(i, j)] = t * rs;
        }
    }
    return prod;
}

__device__ __forceinline__ float fwd6(const float* L, const float* inv, const float* q, float* y)
{
    float ysq = 0.f;
    #pragma unroll
    for (int i = 0; i < LF; i++) {
        float t = q[i];
        #pragma unroll
        for (int m = 0; m < i; m++) t = fmaf(-L[IJ(i, m)], y[m], t);
        y[i] = t * inv[i];
        ysq = fmaf(y[i], y[i], ysq);
    }
    return ysq;
}

struct Slot { float4 h; float2 xj; float ns; unsigned jfh; };

__device__ __forceinline__ void load_slot(Slot& s, const float4* __restrict__ ph,
                                          const float* __restrict__ pn,
                                          const float2* __restrict__ sxj,
                                          const unsigned* __restrict__ sjf, int d)
{
    s.h = ph[d]; s.ns = pn[d]; s.xj = sxj[d]; s.jfh = sjf[d];
}

__device__ __forceinline__ void consume(const Slot& c, u64* acc)
{
    float2 jfv = u2f2(c.jfh);
    u64 jf2 = pk2(jfv.x, jfv.y);
    u64 xj2 = pk2(c.xj.x, c.xj.y);
    const float s = c.h.w;
    u64 e2 = fma2(rep2(c.ns), jf2, mul2(rep2(s), xj2));   // sqrt(invD)*masked residual
    acc[27] = fma2(e2, e2, acc[27]);                       // quad
    float ld = __log2f(s) * (-1.38629436112f);             // recover logD = -2 ln(s)
    acc[28] = fma2(jf2, rep2(ld), acc[28]);                // Jf . logD

    float2 c01 = bits2f2(c.h.x), c23 = bits2f2(c.h.y), c45 = bits2f2(c.h.z);
    u64 c2[LF] = { rep2(c01.x), rep2(c01.y), rep2(c23.x),
                   rep2(c23.y), rep2(c45.x), rep2(c45.y) };
    #pragma unroll
    for (int i = 0; i < LF; i++) {
        acc[21 + i] = fma2(e2, c2[i], acc[21 + i]);        // q
        u64 jc = mul2(jf2, c2[i]);
        #pragma unroll
        for (int j = 0; j <= i; j++)
            acc[IJ(i, j)] = fma2(jc, c2[j], acc[IJ(i, j)]); // P
    }
}

__global__ __launch_bounds__(THREADS, 3)
void mfa_main(const float* __restrict__ X, const int* __restrict__ J,
              const float* __restrict__ MU, const float* __restrict__ A_fac,
              const float* __restrict__ log_D, const float* __restrict__ PI,
              float* __restrict__ outPw, float* __restrict__ outM,
              float* __restrict__ outA, float* __restrict__ outD)
{
    __shared__ float2   s_xj[DP + PAD];        // {xj0, xj1}
    __shared__ unsigned s_jfh[DP + PAD];       // half2 {jf0, jf1}
    __shared__ float    s_pi[KC];
    __shared__ float2   s_top[NWARPS][NB][2];  // {score, k-as-float} top-2 per warp
    __shared__ int      s_cand[NB][NCAND];
    __shared__ float    s_exsc[NB * NCAND];
    __shared__ float    s_exPq[NB * NCAND][27];
    __shared__ float    s_mz[NB][LF];
    __shared__ float    s_Lzm[NB][21];
    __shared__ int      s_c[NB];

    const int tid  = threadIdx.x;
    const int lane = tid & 31;
    const int warp = tid >> 5;
    const int b0   = blockIdx.x * NB;

    for (int t = tid; t < DP + PAD; t += THREADS) {
        if (t < DFT) {
            float x0  = X[(size_t)b0 * DFT + t];
            float x1  = X[(size_t)(b0 + 1) * DFT + t];
            float jf0 = (J[(size_t)b0 * DFT + t] == 1) ? 1.0f : 0.0f;
            float jf1 = (J[(size_t)(b0 + 1) * DFT + t] == 1) ? 1.0f : 0.0f;
            s_xj[t] = make_float2(x0 * jf0, x1 * jf1);
            __half2 h = __floats2half2_rn(jf0, jf1);
            s_jfh[t] = *reinterpret_cast<unsigned*>(&h);
        } else {
            s_xj[t] = make_float2(0.f, 0.f);
            s_jfh[t] = 0u;
        }
    }
    for (int t = tid; t < KC; t += THREADS) s_pi[t] = PI[t];
    __syncthreads();

    // ---- Phase 1 (approx, fp16 operands): warp w owns k = w, w+5, ... ----
    float bs1[NB] = {-1e30f, -1e30f}, bs2[NB] = {-1e30f, -1e30f};
    int   bk1[NB] = {0, 0},           bk2[NB] = {0, 0};

    for (int k = warp; k < KC; k += NWARPS) {
        u64 acc[29];
        #pragma unroll
        for (int t = 0; t < 29; t++) acc[t] = 0ull;

        const float4*   __restrict__ ph = g_H  + (size_t)k * DP;
        const float*    __restrict__ pn = g_NS + (size_t)k * DP;

        Slot s0, s1;
        load_slot(s0, ph, pn, s_xj, s_jfh, lane);
        load_slot(s1, ph, pn, s_xj, s_jfh, lane + 32);

        #pragma unroll 2
        for (int t = 0; t < NITER - 1; t += 2) {
            int d = lane + 32 * t;
            Slot c0 = s0;
            load_slot(s0, ph, pn, s_xj, s_jfh, d + 64);
            consume(c0, acc);
            Slot c1 = s1;
            load_slot(s1, ph, pn, s_xj, s_jfh, d + 96);
            consume(c1, acc);
        }
        consume(s0, acc);

        #pragma unroll
        for (int t = 0; t < 29; t++) {
            u64 v = acc[t];
            #pragma unroll
            for (int off = 16; off > 0; off >>= 1)
                v = add2(v, __shfl_xor_sync(0xffffffffu, v, off));
            acc[t] = v;
        }

        if (lane == 0) {
            float av[29][NB];
            #pragma unroll
            for (int t = 0; t < 29; t++) upk2(acc[t], av[t][0], av[t][1]);
            #pragma unroll
            for (int b2 = 0; b2 < NB; b2++) {
                float P[21], q[LF];
                #pragma unroll
                for (int t = 0; t < 21; t++) P[t] = av[t][b2];
                #pragma unroll
                for (int i = 0; i < LF; i++) { P[IJ(i, i)] += 1.0f; q[i] = av[21 + i][b2]; }
                float inv[LF];
                float prod = chol6(P, inv);
                float y[LF];
                float ysq = fwd6(P, inv, q, y);
                float score = s_pi[k] - 0.5f * (av[27][b2] - ysq + __logf(prod) + av[28][b2]);
                if (score > bs1[b2])      { bs2[b2] = bs1[b2]; bk2[b2] = bk1[b2];
                                            bs1[b2] = score;   bk1[b2] = k; }
                else if (score > bs2[b2]) { bs2[b2] = score;   bk2[b2] = k; }
            }
        }
    }
    if (lane == 0) {
        #pragma unroll
        for (int b2 = 0; b2 < NB; b2++) {
            s_top[warp][b2][0] = make_float2(bs1[b2], __int_as_float(bk1[b2]));
            s_top[warp][b2][1] = make_float2(bs2[b2], __int_as_float(bk2[b2]));
        }
    }
    __syncthreads();

    // ---- Phase 2a: merge warp candidates -> global approx top-3 per sample ----
    if (tid < NB) {
        const int b2 = tid;
        float ts[NCAND] = {-1e30f, -1e30f, -1e30f};
        int   tk[NCAND] = {0, 0, 0};
        for (int w = 0; w < NWARPS; w++)
            for (int e = 0; e < 2; e++) {
                float sc = s_top[w][b2][e].x;
                int   kk = __float_as_int(s_top[w][b2][e].y);
                if (sc > ts[0])      { ts[2]=ts[1]; tk[2]=tk[1]; ts[1]=ts[0]; tk[1]=tk[0]; ts[0]=sc; tk[0]=kk; }
                else if (sc > ts[1]) { ts[2]=ts[1]; tk[2]=tk[1]; ts[1]=sc; tk[1]=kk; }
                else if (sc > ts[2]) { ts[2]=sc; tk[2]=kk; }
            }
        #pragma unroll
        for (int c = 0; c < NCAND; c++) s_cand[b2][c] = tk[c];
    }
    __syncthreads();

    // ---- Phase 2b: exact fp32 rescore of top-3 candidates (one warp per task) ----
    for (int task = warp; task < NB * NCAND; task += NWARPS) {
        const int b2 = task % NB;
        const int cd = task / NB;
        const int k  = s_cand[b2][cd];
        const float4* __restrict__ p0 = g_C0 + (size_t)k * DP;
        const float4* __restrict__ p1 = g_C1 + (size_t)k * DP;
        const float*  __restrict__ pl = g_LD + (size_t)k * DP;

        float a[29];
        #pragma unroll
        for (int t = 0; t < 29; t++) a[t] = 0.f;

        for (int d = lane; d < DP; d += 32) {
            float4 v0 = p0[d], v1 = p1[d];
            float ldv = pl[d];
            float2 xj = s_xj[d];
            float2 jfv = u2f2(s_jfh[d]);
            float jf  = b2 ? jfv.y : jfv.x;
            float xjb = b2 ? xj.y  : xj.x;
            float c[LF] = {v0.x, v0.y, v0.z, v0.w, v1.x, v1.y};
            float e = fmaf(v1.w, jf, v1.z * xjb);   // nsmu*jf + s*xj (matches R3 order)
            a[27] = fmaf(e, e, a[27]);
            a[28] = fmaf(jf, ldv, a[28]);
            #pragma unroll
            for (int i = 0; i < LF; i++) {
                a[21 + i] = fmaf(e, c[i], a[21 + i]);
                float jc = jf * c[i];
                #pragma unroll
                for (int j = 0; j <= i; j++)
                    a[IJ(i, j)] = fmaf(jc, c[j], a[IJ(i, j)]);
            }
        }
        #pragma unroll
        for (int t = 0; t < 29; t++) {
            float v = a[t];
            #pragma unroll
            for (int off = 16; off > 0; off >>= 1)
                v += __shfl_xor_sync(0xffffffffu, v, off);
            a[t] = v;
        }
        if (lane == 0) {
            float P[21], q[LF];
            #pragma unroll
            for (int t = 0; t < 21; t++) P[t] = a[t];
            #pragma unroll
            for (int i = 0; i < LF; i++) { P[IJ(i, i)] += 1.0f; q[i] = a[21 + i]; }
            float inv[LF];
            float prod = chol6(P, inv);
            float y[LF];
            float ysq = fwd6(P, inv, q, y);
            s_exsc[task] = s_pi[k] - 0.5f * (a[27] - ysq + __logf(prod) + a[28]);
            #pragma unroll
            for (int t = 0; t < 21; t++) s_exPq[task][t] = a[t];
            #pragma unroll
            for (int i = 0; i < LF; i++) s_exPq[task][21 + i] = a[21 + i];
        }
    }
    __syncthreads();

    // ---- Phase 2c: pick exact winner, do small linalg ----
    if (tid < NB) {
        const int b2 = tid;
        int wc = 0; float best = -1e30f;
        for (int cdd = 0; cdd < NCAND; cdd++) {
            float sc = s_exsc[cdd * NB + b2];
            if (sc > best) { best = sc; wc = cdd; }
        }
        const int task = wc * NB + b2;
        s_c[b2] = s_cand[b2][wc];

        float P[21], q[LF];
        #pragma unroll
        for (int t = 0; t < 21; t++) P[t] = s_exPq[task][t];
        #pragma unroll
        for (int i = 0; i < LF; i++) { P[IJ(i, i)] += 1.0f; q[i] = s_exPq[task][21 + i]; }

        float inv[LF];
        (void)chol6(P, inv);
        float y[LF];
        (void)fwd6(P, inv, q, y);
        float mz[LF];
        #pragma unroll
        for (int ii = LF - 1; ii >= 0; ii--) {
            float t = y[ii];
            #pragma unroll
            for (int m = ii + 1; m < LF; m++) t = fmaf(-P[IJ(m, ii)], mz[m], t);
            mz[ii] = t * inv[ii];
        }
        float Li[21];
        #pragma unroll
        for (int j = 0; j < LF; j++) {
            Li[IJ(j, j)] = inv[j];
            #pragma unroll
            for (int i = j + 1; i < LF; i++) {
                float t = 0.f;
                #pragma unroll
                for (int m = j; m < i; m++) t = fmaf(P[IJ(i, m)], Li[IJ(m, j)], t);
                Li[IJ(i, j)] = -inv[i] * t;
            }
        }
        float C[21];
        #pragma unroll
        for (int i = 0; i < LF; i++)
            #pragma unroll
            for (int j = 0; j <= i; j++) {
                float t = 0.f;
                #pragma unroll
                for (int m = i; m < LF; m++) t = fmaf(Li[IJ(m, i)], Li[IJ(m, j)], t);
                C[IJ(i, j)] = t;
            }
        float invz[LF];
        (void)chol6(C, invz);
        #pragma unroll
        for (int i = 0; i < LF; i++) s_mz[b2][i] = mz[i];
        #pragma unroll
        for (int t = 0; t < 21; t++) s_Lzm[b2][t] = C[t];
    }
    __syncthreads();

    // ---- Epilogue: stream outputs (exact original inputs) ----
    #pragma unroll
    for (int b2 = 0; b2 < NB; b2++) {
        const int b = b0 + b2;
        const int c = s_c[b2];
        float mz[LF], Lz[21];
        #pragma unroll
        for (int i = 0; i < LF; i++) mz[i] = s_mz[b2][i];
        #pragma unroll
        for (int t = 0; t < 21; t++) Lz[t] = s_Lzm[b2][t];
        const float* __restrict__ ac  = A_fac + (size_t)c * DFT * LF;
        const float* __restrict__ muc = MU    + (size_t)c * DFT;
        const float* __restrict__ ldc = log_D + (size_t)c * DFT;
        for (int d = tid; d < DFT; d += THREADS) {
            const float2* ar = reinterpret_cast<const float2*>(ac + (size_t)d * LF);
            float2 r0 = ar[0], r1 = ar[1], r2 = ar[2];
            float a[LF] = {r0.x, r0.y, r1.x, r1.y, r2.x, r2.y};
            float Mo = muc[d];
            #pragma unroll
            for (int i = 0; i < LF; i++) Mo = fmaf(a[i], mz[i], Mo);
            outM[(size_t)b * DFT + d] = Mo;
            float Ao[LF];
            #pragma unroll
            for (int j = 0; j < LF; j++) {
                float s = 0.f;
                #pragma unroll
                for (int i = j; i < LF; i++) s = fmaf(a[i], Lz[IJ(i, j)], s);
                Ao[j] = s;
            }
            float2* pA = reinterpret_cast<float2*>(outA + ((size_t)b * DFT + d) * LF);
            pA[0] = make_float2(Ao[0], Ao[1]);
            pA[1] = make_float2(Ao[2], Ao[3]);
            pA[2] = make_float2(Ao[4], Ao[5]);
            outD[(size_t)b * DFT + d] = expf(ldc[d]);
        }
    }
    if (tid < NB) outPw[b0 + tid] = 1.0f;
}

extern "C" void kernel_launch(void* const* d_in, const int* in_sizes, int n_in,
                              void* d_out, int out_size)
{
    const float* X      = (const float*)d_in[0];
    const int*   J      = (const int*)  d_in[1];
    const float* MU     = (const float*)d_in[2];
    const float* A_fac  = (const float*)d_in[3];
    const float* log_D  = (const float*)d_in[4];
    const float* PI     = (const float*)d_in[5];
    float* out = (float*)d_out;

    const int B = in_sizes[0] / DFT;     // 2048
    float* outPw = out;
    float* outM  = out + B;
    float* outA  = outM + (size_t)B * DFT;
    float* outD  = outA + (size_t)B * DFT * LF;

    pack_kernel<<<(KC * DP + PAD + 255) / 256, 256>>>(A_fac, MU, log_D);
    mfa_main<<<B / NB, THREADS>>>(X, J, MU, A_fac, log_D, PI, outPw, outM, outA, outD);
}

// round 5
// speedup vs baseline: 1.2403x; 1.2403x over previous
#include <cuda_runtime.h>

#define DFT 784
#define DP  800              // padded feature dim (zero-padded tail)
#define PAD 64               // over-allocation so prefetch needs no guard
#define KC  50
#define LF  6
#define NB  2
#define THREADS 128
#define NWARPS (THREADS/32)  // 4 -> warps own 13/13/12/12 components
#define NITER 25             // DP/32

typedef unsigned long long u64;

// SoA packed operands, coalesced per warp:
//  g_C0[k*DP+d] = {c0,c1,c2,c3},  g_C1[k*DP+d] = {c4,c5,s,nsmu},  g_LD[k*DP+d] = logD
// where c_i = sqrt(invD)*a_i, s = sqrt(invD), nsmu = -s*mu.
__device__ __align__(16) float4 g_C0[KC * DP + PAD];
__device__ __align__(16) float4 g_C1[KC * DP + PAD];
__device__ float g_LD[KC * DP + PAD];

__device__ __forceinline__ constexpr int IJ(int i, int j) { return i * (i + 1) / 2 + j; }

// ---- f32x2 packed helpers ----
__device__ __forceinline__ u64 pk2(float a, float b) {
    u64 r; asm("mov.b64 %0,{%1,%2};" : "=l"(r) : "f"(a), "f"(b)); return r;
}
__device__ __forceinline__ u64 rep2(float a) { return pk2(a, a); }
__device__ __forceinline__ void upk2(u64 v, float& a, float& b) {
    asm("mov.b64 {%0,%1},%2;" : "=f"(a), "=f"(b) : "l"(v));
}
__device__ __forceinline__ u64 fma2(u64 a, u64 b, u64 c) {
    u64 d; asm("fma.rn.f32x2 %0,%1,%2,%3;" : "=l"(d) : "l"(a), "l"(b), "l"(c)); return d;
}
__device__ __forceinline__ u64 mul2(u64 a, u64 b) {
    u64 d; asm("mul.rn.f32x2 %0,%1,%2;" : "=l"(d) : "l"(a), "l"(b)); return d;
}
__device__ __forceinline__ u64 add2(u64 a, u64 b) {
    u64 d; asm("add.rn.f32x2 %0,%1,%2;" : "=l"(d) : "l"(a), "l"(b)); return d;
}

__global__ void pack_kernel(const float* __restrict__ A_fac,
                            const float* __restrict__ MU,
                            const float* __restrict__ log_D)
{
    int idx = blockIdx.x * blockDim.x + threadIdx.x;
    if (idx >= KC * DP + PAD) return;
    int k = idx / DP, d = idx - k * DP;
    if (k < KC && d < DFT) {
        int src = k * DFT + d;
        const float* a = A_fac + (size_t)src * LF;
        float ld = log_D[src];
        float s  = expf(-0.5f * ld);       // sqrt(invD)
        g_C0[idx] = make_float4(s * a[0], s * a[1], s * a[2], s * a[3]);
        g_C1[idx] = make_float4(s * a[4], s * a[5], s, -s * MU[src]);
        g_LD[idx] = ld;
    } else {
        g_C0[idx] = make_float4(0.f, 0.f, 0.f, 0.f);
        g_C1[idx] = make_float4(0.f, 0.f, 0.f, 0.f);
        g_LD[idx] = 0.f;
    }
}

// Cholesky (lower) of packed 6x6 SPD, in place. Returns product of pivots (= det),
// fills inv[j] = 1/L[j][j].
__device__ __forceinline__ float chol6(float* S, float* inv)
{
    float prod = 1.f;
    #pragma unroll
    for (int j = 0; j < LF; j++) {
        float s = S[IJ(j, j)];
        #pragma unroll
        for (int m = 0; m < j; m++) s = fmaf(-S[IJ(j, m)], S[IJ(j, m)], s);
        prod *= s;
        float rs = rsqrtf(s);
        inv[j] = rs;
        S[IJ(j, j)] = s * rs;
        #pragma unroll
        for (int i = j + 1; i < LF; i++) {
            float t = S[IJ(i, j)];
            #pragma unroll
            for (int m = 0; m < j; m++) t = fmaf(-S[IJ(i, m)], S[IJ(j, m)], t);
            S[IJ(i, j)] = t * rs;
        }
    }
    return prod;
}

__device__ __forceinline__ float fwd6(const float* L, const float* inv, const float* q, float* y)
{
    float ysq = 0.f;
    #pragma unroll
    for (int i = 0; i < LF; i++) {
        float t = q[i];
        #pragma unroll
        for (int m = 0; m < i; m++) t = fmaf(-L[IJ(i, m)], y[m], t);
        y[i] = t * inv[i];
        ysq = fmaf(y[i], y[i], ysq);
    }
    return ysq;
}

// Prefetch slots carry only the two LDG.128 streams (L2-latency bound).
struct Slot { float4 v0, v1; };

__device__ __forceinline__ void load_slot(Slot& s, const float4* __restrict__ p0,
                                          const float4* __restrict__ p1, int d)
{
    s.v0 = p0[d]; s.v1 = p1[d];
}

__device__ __forceinline__ void consume(const Slot& c, float ld, float4 in, u64* acc)
{
    u64 jf2 = pk2(in.x, in.y);
    u64 xj2 = pk2(in.z, in.w);
    u64 c2[LF] = { rep2(c.v0.x), rep2(c.v0.y), rep2(c.v0.z),
                   rep2(c.v0.w), rep2(c.v1.x), rep2(c.v1.y) };

    u64 e2 = fma2(rep2(c.v1.w), jf2, mul2(rep2(c.v1.z), xj2)); // nsmu*jf + s*xj
    acc[27] = fma2(e2, e2, acc[27]);               // quad
    acc[28] = fma2(jf2, rep2(ld), acc[28]);        // Jf . logD

    #pragma unroll
    for (int i = 0; i < LF; i++) {
        acc[21 + i] = fma2(e2, c2[i], acc[21 + i]);    // q
        u64 jc = mul2(jf2, c2[i]);
        #pragma unroll
        for (int j = 0; j <= i; j++)
            acc[IJ(i, j)] = fma2(jc, c2[j], acc[IJ(i, j)]);  // P
    }
}

__global__ __launch_bounds__(THREADS, 4)
void mfa_main(const float* __restrict__ X, const int* __restrict__ J,
              const float* __restrict__ MU, const float* __restrict__ A_fac,
              const float* __restrict__ log_D, const float* __restrict__ PI,
              float* __restrict__ outPw, float* __restrict__ outM,
              float* __restrict__ outA, float* __restrict__ outD)
{
    __shared__ float4 s_in[DP + PAD];          // {jf0, jf1, xj0, xj1}
    __shared__ float  s_pi[KC];
    __shared__ float  s_bscore[NWARPS][NB];
    __shared__ int    s_bk[NWARPS][NB];
    __shared__ float  s_bPq[NWARPS][NB][27];
    __shared__ float  s_mz[NB][LF];
    __shared__ float  s_Lzm[NB][21];
    __shared__ int    s_c[NB];

    const int tid  = threadIdx.x;
    const int lane = tid & 31;
    const int warp = tid >> 5;
    const int b0   = blockIdx.x * NB;

    for (int t = tid; t < DP + PAD; t += THREADS) {
        if (t < DFT) {
            float x0  = X[(size_t)b0 * DFT + t];
            float x1  = X[(size_t)(b0 + 1) * DFT + t];
            float jf0 = (J[(size_t)b0 * DFT + t] == 1) ? 1.0f : 0.0f;
            float jf1 = (J[(size_t)(b0 + 1) * DFT + t] == 1) ? 1.0f : 0.0f;
            s_in[t] = make_float4(jf0, jf1, x0 * jf0, x1 * jf1);
        } else {
            s_in[t] = make_float4(0.f, 0.f, 0.f, 0.f);
        }
    }
    for (int t = tid; t < KC; t += THREADS) s_pi[t] = PI[t];
    if (lane == 0) {
        s_bscore[warp][0] = -1e30f;
        s_bscore[warp][1] = -1e30f;
    }
    __syncthreads();

    // ---- Phase 1: warp w owns k = w, w+4, ... (13/13/12/12 components) ----
    for (int k = warp; k < KC; k += NWARPS) {
        u64 acc[29];
        #pragma unroll
        for (int t = 0; t < 29; t++) acc[t] = 0ull;

        const float4* __restrict__ p0 = g_C0 + (size_t)k * DP;
        const float4* __restrict__ p1 = g_C1 + (size_t)k * DP;
        const float*  __restrict__ pl = g_LD + (size_t)k * DP;

        Slot s0, s1;
        load_slot(s0, p0, p1, lane);
        load_slot(s1, p0, p1, lane + 32);

        // Prefetch distance 2 on the LDG streams; smem + logD read in-loop.
        #pragma unroll 2
        for (int t = 0; t < NITER - 1; t += 2) {
            int d = lane + 32 * t;
            Slot c0 = s0;
            load_slot(s0, p0, p1, d + 64);
            consume(c0, pl[d], s_in[d], acc);
            Slot c1 = s1;
            load_slot(s1, p0, p1, d + 96);
            consume(c1, pl[d + 32], s_in[d + 32], acc);
        }
        {
            int d = lane + 32 * (NITER - 1);
            consume(s0, pl[d], s_in[d], acc);
        }

        // Warp butterfly reduce on packed pairs
        #pragma unroll
        for (int t = 0; t < 29; t++) {
            u64 v = acc[t];
            #pragma unroll
            for (int off = 16; off > 0; off >>= 1)
                v = add2(v, __shfl_xor_sync(0xffffffffu, v, off));
            acc[t] = v;
        }

        if (lane == 0) {
            float av[29][NB];
            #pragma unroll
            for (int t = 0; t < 29; t++) upk2(acc[t], av[t][0], av[t][1]);
            #pragma unroll
            for (int b2 = 0; b2 < NB; b2++) {
                float P[21], q[LF];
                #pragma unroll
                for (int t = 0; t < 21; t++) P[t] = av[t][b2];
                #pragma unroll
                for (int i = 0; i < LF; i++) { P[IJ(i, i)] += 1.0f; q[i] = av[21 + i][b2]; }
                float inv[LF];
                float prod = chol6(P, inv);
                float y[LF];
                float ysq = fwd6(P, inv, q, y);
                float score = s_pi[k] - 0.5f * (av[27][b2] - ysq + __logf(prod) + av[28][b2]);
                if (score > s_bscore[warp][b2]) {
                    s_bscore[warp][b2] = score;
                    s_bk[warp][b2] = k;
                    #pragma unroll
                    for (int t = 0; t < 21; t++) s_bPq[warp][b2][t] = av[t][b2];
                    #pragma unroll
                    for (int i = 0; i < LF; i++) s_bPq[warp][b2][21 + i] = q[i];
                }
            }
        }
    }
    __syncthreads();

    // ---- Phase 2: per-sample small linalg ----
    if (tid < NB) {
        const int b2 = tid;
        float best = -1e30f; int bw = 0;
        for (int w = 0; w < NWARPS; w++)
            if (s_bscore[w][b2] > best) { best = s_bscore[w][b2]; bw = w; }
        s_c[b2] = s_bk[bw][b2];

        float P[21], q[LF];
        #pragma unroll
        for (int t = 0; t < 21; t++) P[t] = s_bPq[bw][b2][t];
        #pragma unroll
        for (int i = 0; i < LF; i++) { P[IJ(i, i)] += 1.0f; q[i] = s_bPq[bw][b2][21 + i]; }

        float inv[LF];
        (void)chol6(P, inv);
        float y[LF];
        (void)fwd6(P, inv, q, y);
        float mz[LF];
        #pragma unroll
        for (int ii = LF - 1; ii >= 0; ii--) {
            float t = y[ii];
            #pragma unroll
            for (int m = ii + 1; m < LF; m++) t = fmaf(-P[IJ(m, ii)], mz[m], t);
            mz[ii] = t * inv[ii];
        }
        float Li[21];
        #pragma unroll
        for (int j = 0; j < LF; j++) {
            Li[IJ(j, j)] = inv[j];
            #pragma unroll
            for (int i = j + 1; i < LF; i++) {
                float t = 0.f;
                #pragma unroll
                for (int m = j; m < i; m++) t = fmaf(P[IJ(i, m)], Li[IJ(m, j)], t);
                Li[IJ(i, j)] = -inv[i] * t;
            }
        }
        float C[21];
        #pragma unroll
        for (int i = 0; i < LF; i++)
            #pragma unroll
            for (int j = 0; j <= i; j++) {
                float t = 0.f;
                #pragma unroll
                for (int m = i; m < LF; m++) t = fmaf(Li[IJ(m, i)], Li[IJ(m, j)], t);
                C[IJ(i, j)] = t;
            }
        float invz[LF];
        (void)chol6(C, invz);
        #pragma unroll
        for (int i = 0; i < LF; i++) s_mz[b2][i] = mz[i];
        #pragma unroll
        for (int t = 0; t < 21; t++) s_Lzm[b2][t] = C[t];
    }
    __syncthreads();

    // ---- Epilogue: stream outputs (exact original inputs) ----
    #pragma unroll
    for (int b2 = 0; b2 < NB; b2++) {
        const int b = b0 + b2;
        const int c = s_c[b2];
        float mz[LF], Lz[21];
        #pragma unroll
        for (int i = 0; i < LF; i++) mz[i] = s_mz[b2][i];
        #pragma unroll
        for (int t = 0; t < 21; t++) Lz[t] = s_Lzm[b2][t];
        const float* __restrict__ ac  = A_fac + (size_t)c * DFT * LF;
        const float* __restrict__ muc = MU    + (size_t)c * DFT;
        const float* __restrict__ ldc = log_D + (size_t)c * DFT;
        for (int d = tid; d < DFT; d += THREADS) {
            const float2* ar = reinterpret_cast<const float2*>(ac + (size_t)d * LF);
            float2 r0 = ar[0], r1 = ar[1], r2 = ar[2];
            float a[LF] = {r0.x, r0.y, r1.x, r1.y, r2.x, r2.y};
            float Mo = muc[d];
            #pragma unroll
            for (int i = 0; i < LF; i++) Mo = fmaf(a[i], mz[i], Mo);
            outM[(size_t)b * DFT + d] = Mo;
            float Ao[LF];
            #pragma unroll
            for (int j = 0; j < LF; j++) {
                float s = 0.f;
                #pragma unroll
                for (int i = j; i < LF; i++) s = fmaf(a[i], Lz[IJ(i, j)], s);
                Ao[j] = s;
            }
            float2* pA = reinterpret_cast<float2*>(outA + ((size_t)b * DFT + d) * LF);
            pA[0] = make_float2(Ao[0], Ao[1]);
            pA[1] = make_float2(Ao[2], Ao[3]);
            pA[2] = make_float2(Ao[4], Ao[5]);
            outD[(size_t)b * DFT + d] = expf(ldc[d]);
        }
    }
    if (tid < NB) outPw[b0 + tid] = 1.0f;
}

extern "C" void kernel_launch(void* const* d_in, const int* in_sizes, int n_in,
                              void* d_out, int out_size)
{
    const float* X      = (const float*)d_in[0];
    const int*   J      = (const int*)  d_in[1];
    const float* MU     = (const float*)d_in[2];
    const float* A_fac  = (const float*)d_in[3];
    const float* log_D  = (const float*)d_in[4];
    const float* PI     = (const float*)d_in[5];
    float* out = (float*)d_out;

    const int B = in_sizes[0] / DFT;     // 2048
    float* outPw = out;
    float* outM  = out + B;
    float* outA  = outM + (size_t)B * DFT;
    float* outD  = outA + (size_t)B * DFT * LF;

    pack_kernel<<<(KC * DP + PAD + 255) / 256, 256>>>(A_fac, MU, log_D);
    mfa_main<<<B / NB, THREADS>>>(X, J, MU, A_fac, log_D, PI, outPw, outM, outA, outD);
}

// round 6
// speedup vs baseline: 1.6852x; 1.3587x over previous
#include <cuda_runtime.h>

#define DFT 784
#define DP  800              // padded feature dim (zero-padded tail)
#define PAD 64               // over-allocation so prefetch needs no guard
#define KC  50
#define LF  6
#define NB  2
#define THREADS 128
#define NWARPS (THREADS/32)  // 4 -> warps own 13/13/12/12 components
#define NITER 25             // DP/32
#define STW 30               // padded stats stride (29 -> 30 to spread banks)

typedef unsigned long long u64;

// SoA packed operands, coalesced per warp:
//  g_C0[k*DP+d] = {c0,c1,c2,c3},  g_C1[k*DP+d] = {c4,c5,s,nsmu},  g_LD[k*DP+d] = logD
// where c_i = sqrt(invD)*a_i, s = sqrt(invD), nsmu = -s*mu.
__device__ __align__(16) float4 g_C0[KC * DP + PAD];
__device__ __align__(16) float4 g_C1[KC * DP + PAD];
__device__ float g_LD[KC * DP + PAD];

__device__ __forceinline__ constexpr int IJ(int i, int j) { return i * (i + 1) / 2 + j; }

// ---- f32x2 packed helpers ----
__device__ __forceinline__ u64 pk2(float a, float b) {
    u64 r; asm("mov.b64 %0,{%1,%2};" : "=l"(r) : "f"(a), "f"(b)); return r;
}
__device__ __forceinline__ u64 rep2(float a) { return pk2(a, a); }
__device__ __forceinline__ void upk2(u64 v, float& a, float& b) {
    asm("mov.b64 {%0,%1},%2;" : "=f"(a), "=f"(b) : "l"(v));
}
__device__ __forceinline__ u64 fma2(u64 a, u64 b, u64 c) {
    u64 d; asm("fma.rn.f32x2 %0,%1,%2,%3;" : "=l"(d) : "l"(a), "l"(b), "l"(c)); return d;
}
__device__ __forceinline__ u64 mul2(u64 a, u64 b) {
    u64 d; asm("mul.rn.f32x2 %0,%1,%2;" : "=l"(d) : "l"(a), "l"(b)); return d;
}

__global__ void pack_kernel(const float* __restrict__ A_fac,
                            const float* __restrict__ MU,
                            const float* __restrict__ log_D)
{
    int idx = blockIdx.x * blockDim.x + threadIdx.x;
    if (idx >= KC * DP + PAD) return;
    int k = idx / DP, d = idx - k * DP;
    if (k < KC && d < DFT) {
        int src = k * DFT + d;
        const float* a = A_fac + (size_t)src * LF;
        float ld = log_D[src];
        float s  = expf(-0.5f * ld);       // sqrt(invD)
        g_C0[idx] = make_float4(s * a[0], s * a[1], s * a[2], s * a[3]);
        g_C1[idx] = make_float4(s * a[4], s * a[5], s, -s * MU[src]);
        g_LD[idx] = ld;
    } else {
        g_C0[idx] = make_float4(0.f, 0.f, 0.f, 0.f);
        g_C1[idx] = make_float4(0.f, 0.f, 0.f, 0.f);
        g_LD[idx] = 0.f;
    }
}

// Cholesky (lower) of packed 6x6 SPD, in place. Returns product of pivots (= det),
// fills inv[j] = 1/L[j][j].
__device__ __forceinline__ float chol6(float* S, float* inv)
{
    float prod = 1.f;
    #pragma unroll
    for (int j = 0; j < LF; j++) {
        float s = S[IJ(j, j)];
        #pragma unroll
        for (int m = 0; m < j; m++) s = fmaf(-S[IJ(j, m)], S[IJ(j, m)], s);
        prod *= s;
        float rs = rsqrtf(s);
        inv[j] = rs;
        S[IJ(j, j)] = s * rs;
        #pragma unroll
        for (int i = j + 1; i < LF; i++) {
            float t = S[IJ(i, j)];
            #pragma unroll
            for (int m = 0; m < j; m++) t = fmaf(-S[IJ(i, m)], S[IJ(j, m)], t);
            S[IJ(i, j)] = t * rs;
        }
    }
    return prod;
}

__device__ __forceinline__ float fwd6(const float* L, const float* inv, const float* q, float* y)
{
    float ysq = 0.f;
    #pragma unroll
    for (int i = 0; i < LF; i++) {
        float t = q[i];
        #pragma unroll
        for (int m = 0; m < i; m++) t = fmaf(-L[IJ(i, m)], y[m], t);
        y[i] = t * inv[i];
        ysq = fmaf(y[i], y[i], ysq);
    }
    return ysq;
}

// Prefetch slots carry only the two LDG.128 streams (L2-latency bound).
struct Slot { float4 v0, v1; };

__device__ __forceinline__ void load_slot(Slot& s, const float4* __restrict__ p0,
                                          const float4* __restrict__ p1, int d)
{
    s.v0 = p0[d]; s.v1 = p1[d];
}

__device__ __forceinline__ void consume(const Slot& c, float ld, float4 in, u64* acc)
{
    u64 jf2 = pk2(in.x, in.y);
    u64 xj2 = pk2(in.z, in.w);
    u64 c2[LF] = { rep2(c.v0.x), rep2(c.v0.y), rep2(c.v0.z),
                   rep2(c.v0.w), rep2(c.v1.x), rep2(c.v1.y) };

    u64 e2 = fma2(rep2(c.v1.w), jf2, mul2(rep2(c.v1.z), xj2)); // nsmu*jf + s*xj
    acc[27] = fma2(e2, e2, acc[27]);               // quad
    acc[28] = fma2(jf2, rep2(ld), acc[28]);        // Jf . logD

    #pragma unroll
    for (int i = 0; i < LF; i++) {
        acc[21 + i] = fma2(e2, c2[i], acc[21 + i]);    // q
        u64 jc = mul2(jf2, c2[i]);
        #pragma unroll
        for (int j = 0; j <= i; j++)
            acc[IJ(i, j)] = fma2(jc, c2[j], acc[IJ(i, j)]);  // P
    }
}

__global__ __launch_bounds__(THREADS, 4)
void mfa_main(const float* __restrict__ X, const int* __restrict__ J,
              const float* __restrict__ MU, const float* __restrict__ A_fac,
              const float* __restrict__ log_D, const float* __restrict__ PI,
              float* __restrict__ outPw, float* __restrict__ outM,
              float* __restrict__ outA, float* __restrict__ outD)
{
    __shared__ float4 s_in[DP + PAD];          // {jf0, jf1, xj0, xj1}
    __shared__ float  s_pi[KC];
    __shared__ float  s_stats[KC][NB][STW];    // raw sums: P 21, q 6, quad, jlogd
    __shared__ float  s_score[KC * NB];
    __shared__ float  s_mz[NB][LF];
    __shared__ float  s_Lzm[NB][21];
    __shared__ int    s_c[NB];

    const int tid  = threadIdx.x;
    const int lane = tid & 31;
    const int warp = tid >> 5;
    const int b0   = blockIdx.x * NB;

    for (int t = tid; t < DP + PAD; t += THREADS) {
        if (t < DFT) {
            float x0  = X[(size_t)b0 * DFT + t];
            float x1  = X[(size_t)(b0 + 1) * DFT + t];
            float jf0 = (J[(size_t)b0 * DFT + t] == 1) ? 1.0f : 0.0f;
            float jf1 = (J[(size_t)(b0 + 1) * DFT + t] == 1) ? 1.0f : 0.0f;
            s_in[t] = make_float4(jf0, jf1, x0 * jf0, x1 * jf1);
        } else {
            s_in[t] = make_float4(0.f, 0.f, 0.f, 0.f);
        }
    }
    for (int t = tid; t < KC; t += THREADS) s_pi[t] = PI[t];
    __syncthreads();

    // ---- Phase 1: accumulate raw stats; warp w owns k = w, w+4, ... ----
    for (int k = warp; k < KC; k += NWARPS) {
        u64 acc[29];
        #pragma unroll
        for (int t = 0; t < 29; t++) acc[t] = 0ull;

        const float4* __restrict__ p0 = g_C0 + (size_t)k * DP;
        const float4* __restrict__ p1 = g_C1 + (size_t)k * DP;
        const float*  __restrict__ pl = g_LD + (size_t)k * DP;

        Slot s0, s1;
        load_slot(s0, p0, p1, lane);
        load_slot(s1, p0, p1, lane + 32);

        #pragma unroll 2
        for (int t = 0; t < NITER - 1; t += 2) {
            int d = lane + 32 * t;
            Slot c0 = s0;
            load_slot(s0, p0, p1, d + 64);
            consume(c0, pl[d], s_in[d], acc);
            Slot c1 = s1;
            load_slot(s1, p0, p1, d + 96);
            consume(c1, pl[d + 32], s_in[d + 32], acc);
        }
        {
            int d = lane + 32 * (NITER - 1);
            consume(s0, pl[d], s_in[d], acc);
        }

        // Split-sample reduction:
        // step 1: xor-1 exchange of packed pair; even lanes keep sample-0 partial,
        //         odd lanes sample-1. steps 2..5: plain fp32 butterflies.
        const bool odd = (lane & 1);
        float r[29];
        #pragma unroll
        for (int t = 0; t < 29; t++) {
            u64 o = __shfl_xor_sync(0xffffffffu, acc[t], 1);
            float slo, shi, olo, ohi;
            upk2(acc[t], slo, shi);
            upk2(o, olo, ohi);
            r[t] = odd ? (shi + ohi) : (slo + olo);
        }
        #pragma unroll
        for (int t = 0; t < 29; t++) {
            #pragma unroll
            for (int off = 2; off < 32; off <<= 1)
                r[t] += __shfl_xor_sync(0xffffffffu, r[t], off);
        }
        if (lane < 2) {
            #pragma unroll
            for (int t = 0; t < 29; t++) s_stats[k][lane][t] = r[t];
        }
    }
    __syncthreads();

    // ---- Phase 1.5: block-parallel scoring (100 independent tasks) ----
    if (tid < KC * NB) {
        const int k  = tid >> 1;
        const int b2 = tid & 1;
        float P[21], q[LF];
        #pragma unroll
        for (int t = 0; t < 21; t++) P[t] = s_stats[k][b2][t];
        float quad = s_stats[k][b2][27];
        float jld  = s_stats[k][b2][28];
        #pragma unroll
        for (int i = 0; i < LF; i++) { P[IJ(i, i)] += 1.0f; q[i] = s_stats[k][b2][21 + i]; }
        float inv[LF];
        float prod = chol6(P, inv);
        float y[LF];
        float ysq = fwd6(P, inv, q, y);
        s_score[tid] = s_pi[k] - 0.5f * (quad - ysq + __logf(prod) + jld);
    }
    __syncthreads();

    // ---- Phase 2: select winner (ascending k => first-max) + small linalg ----
    if (tid < NB) {
        const int b2 = tid;
        float best = -1e30f; int bc = 0;
        for (int k = 0; k < KC; k++) {
            float sc = s_score[k * NB + b2];
            if (sc > best) { best = sc; bc = k; }
        }
        s_c[b2] = bc;

        float P[21], q[LF];
        #pragma unroll
        for (int t = 0; t < 21; t++) P[t] = s_stats[bc][b2][t];
        #pragma unroll
        for (int i = 0; i < LF; i++) { P[IJ(i, i)] += 1.0f; q[i] = s_stats[bc][b2][21 + i]; }

        float inv[LF];
        (void)chol6(P, inv);
        float y[LF];
        (void)fwd6(P, inv, q, y);
        float mz[LF];
        #pragma unroll
        for (int ii = LF - 1; ii >= 0; ii--) {
            float t = y[ii];
            #pragma unroll
            for (int m = ii + 1; m < LF; m++) t = fmaf(-P[IJ(m, ii)], mz[m], t);
            mz[ii] = t * inv[ii];
        }
        float Li[21];
        #pragma unroll
        for (int j = 0; j < LF; j++) {
            Li[IJ(j, j)] = inv[j];
            #pragma unroll
            for (int i = j + 1; i < LF; i++) {
                float t = 0.f;
                #pragma unroll
                for (int m = j; m < i; m++) t = fmaf(P[IJ(i, m)], Li[IJ(m, j)], t);
                Li[IJ(i, j)] = -inv[i] * t;
            }
        }
        float C[21];
        #pragma unroll
        for (int i = 0; i < LF; i++)
            #pragma unroll
            for (int j = 0; j <= i; j++) {
                float t = 0.f;
                #pragma unroll
                for (int m = i; m < LF; m++) t = fmaf(Li[IJ(m, i)], Li[IJ(m, j)], t);
                C[IJ(i, j)] = t;
            }
        float invz[LF];
        (void)chol6(C, invz);
        #pragma unroll
        for (int i = 0; i < LF; i++) s_mz[b2][i] = mz[i];
        #pragma unroll
        for (int t = 0; t < 21; t++) s_Lzm[b2][t] = C[t];
    }
    __syncthreads();

    // ---- Epilogue: stream outputs (exact original inputs) ----
    #pragma unroll
    for (int b2 = 0; b2 < NB; b2++) {
        const int b = b0 + b2;
        const int c = s_c[b2];
        float mz[LF], Lz[21];
        #pragma unroll
        for (int i = 0; i < LF; i++) mz[i] = s_mz[b2][i];
        #pragma unroll
        for (int t = 0; t < 21; t++) Lz[t] = s_Lzm[b2][t];
        const float* __restrict__ ac  = A_fac + (size_t)c * DFT * LF;
        const float* __restrict__ muc = MU    + (size_t)c * DFT;
        const float* __restrict__ ldc = log_D + (size_t)c * DFT;
        for (int d = tid; d < DFT; d += THREADS) {
            const float2* ar = reinterpret_cast<const float2*>(ac + (size_t)d * LF);
            float2 r0 = ar[0], r1 = ar[1], r2 = ar[2];
            float a[LF] = {r0.x, r0.y, r1.x, r1.y, r2.x, r2.y};
            float Mo = muc[d];
            #pragma unroll
            for (int i = 0; i < LF; i++) Mo = fmaf(a[i], mz[i], Mo);
            outM[(size_t)b * DFT + d] = Mo;
            float Ao[LF];
            #pragma unroll
            for (int j = 0; j < LF; j++) {
                float s = 0.f;
                #pragma unroll
                for (int i = j; i < LF; i++) s = fmaf(a[i], Lz[IJ(i, j)], s);
                Ao[j] = s;
            }
            float2* pA = reinterpret_cast<float2*>(outA + ((size_t)b * DFT + d) * LF);
            pA[0] = make_float2(Ao[0], Ao[1]);
            pA[1] = make_float2(Ao[2], Ao[3]);
            pA[2] = make_float2(Ao[4], Ao[5]);
            outD[(size_t)b * DFT + d] = expf(ldc[d]);
        }
    }
    if (tid < NB) outPw[b0 + tid] = 1.0f;
}

extern "C" void kernel_launch(void* const* d_in, const int* in_sizes, int n_in,
                              void* d_out, int out_size)
{
    const float* X      = (const float*)d_in[0];
    const int*   J      = (const int*)  d_in[1];
    const float* MU     = (const float*)d_in[2];
    const float* A_fac  = (const float*)d_in[3];
    const float* log_D  = (const float*)d_in[4];
    const float* PI     = (const float*)d_in[5];
    float* out = (float*)d_out;

    const int B = in_sizes[0] / DFT;     // 2048
    float* outPw = out;
    float* outM  = out + B;
    float* outA  = outM + (size_t)B * DFT;
    float* outD  = outA + (size_t)B * DFT * LF;

    pack_kernel<<<(KC * DP + PAD + 255) / 256, 256>>>(A_fac, MU, log_D);
    mfa_main<<<B / NB, THREADS>>>(X, J, MU, A_fac, log_D, PI, outPw, outM, outA, outD);
}